// round 1
// baseline (speedup 1.0000x reference)
#include <cuda_runtime.h>
#include <math.h>

#define H_ 8
#define DMODEL 512
#define DK_ 64
#define NB 4
#define LMAX 2048

// ---------------- scratch (no allocations allowed) ----------------
__device__ float g_q[NB * LMAX * DMODEL];
__device__ float g_k[NB * LMAX * DMODEL];
__device__ float g_v[NB * LMAX * DMODEL];
__device__ float g_o[NB * LMAX * DMODEL];

// ---------------- tiled NT GEMM: C[m,n] = sum_k A[m,k]*W[n,k] + bias[n] ----
// M x N x K, tiles 64x64x32, 256 threads, 4x4 per-thread microtile.
#define GM 64
#define GN 64
#define GK 32
#define GMP 68   // padded stride (floats); 68*4B = 272B, 16B aligned rows

__global__ void __launch_bounds__(256) gemm_nt_bias(
    const float* __restrict__ A, const float* __restrict__ W,
    const float* __restrict__ bias, float* __restrict__ C,
    int M, int N, int K)
{
    __shared__ float As[GK * GMP];
    __shared__ float Bs[GK * GMP];

    const int t  = threadIdx.x;
    const int tx = t & 15;
    const int ty = t >> 4;
    const int m0 = blockIdx.y * GM;
    const int n0 = blockIdx.x * GN;

    const int lr = t >> 2;           // 0..63: row within tile for loading
    const int lk = (t & 3) * 8;      // k-chunk of 8 within 32

    const float* Ap = A + (size_t)(m0 + lr) * K + lk;
    const float* Wp = W + (size_t)(n0 + lr) * K + lk;

    float acc[4][4] = {};

    for (int k0 = 0; k0 < K; k0 += GK) {
        float4 a0 = *(const float4*)(Ap + k0);
        float4 a1 = *(const float4*)(Ap + k0 + 4);
        float4 b0 = *(const float4*)(Wp + k0);
        float4 b1 = *(const float4*)(Wp + k0 + 4);

        As[(lk + 0) * GMP + lr] = a0.x;  As[(lk + 1) * GMP + lr] = a0.y;
        As[(lk + 2) * GMP + lr] = a0.z;  As[(lk + 3) * GMP + lr] = a0.w;
        As[(lk + 4) * GMP + lr] = a1.x;  As[(lk + 5) * GMP + lr] = a1.y;
        As[(lk + 6) * GMP + lr] = a1.z;  As[(lk + 7) * GMP + lr] = a1.w;

        Bs[(lk + 0) * GMP + lr] = b0.x;  Bs[(lk + 1) * GMP + lr] = b0.y;
        Bs[(lk + 2) * GMP + lr] = b0.z;  Bs[(lk + 3) * GMP + lr] = b0.w;
        Bs[(lk + 4) * GMP + lr] = b1.x;  Bs[(lk + 5) * GMP + lr] = b1.y;
        Bs[(lk + 6) * GMP + lr] = b1.z;  Bs[(lk + 7) * GMP + lr] = b1.w;

        __syncthreads();

        #pragma unroll
        for (int kk = 0; kk < GK; kk++) {
            float4 av = *(const float4*)&As[kk * GMP + ty * 4];
            float4 bv = *(const float4*)&Bs[kk * GMP + tx * 4];
            float a4[4] = {av.x, av.y, av.z, av.w};
            float b4[4] = {bv.x, bv.y, bv.z, bv.w};
            #pragma unroll
            for (int i = 0; i < 4; i++)
                #pragma unroll
                for (int j = 0; j < 4; j++)
                    acc[i][j] += a4[i] * b4[j];
        }
        __syncthreads();
    }

    float4 bb = *(const float4*)&bias[n0 + tx * 4];
    float bj[4] = {bb.x, bb.y, bb.z, bb.w};
    #pragma unroll
    for (int i = 0; i < 4; i++) {
        float4 out;
        out.x = acc[i][0] + bj[0];
        out.y = acc[i][1] + bj[1];
        out.z = acc[i][2] + bj[2];
        out.w = acc[i][3] + bj[3];
        *(float4*)&C[(size_t)(m0 + ty * 4 + i) * N + n0 + tx * 4] = out;
    }
}

// ---------------- flash attention (fp32, online softmax) ------------------
// CTA: 64 q-rows of one (batch, head). Loops over 64-wide K/V tiles.
#define AQ 64
#define AK 64
#define AST 68   // padded row stride

__global__ void __launch_bounds__(256) attn_kernel(
    const float* __restrict__ Qb, const float* __restrict__ Kb,
    const float* __restrict__ Vb, const int* __restrict__ mask,
    float* __restrict__ Ob, int L)
{
    extern __shared__ float sm[];
    float* Qs   = sm;                    // AQ x AST
    float* Ks   = Qs + AQ * AST;         // AK x AST
    float* Vs   = Ks + AK * AST;         // AK x AST
    float* Ss   = Vs + AK * AST;         // AQ x AST
    float* mrow = Ss + AQ * AST;         // AQ
    float* lrow = mrow + AQ;             // AQ
    float* srow = lrow + AQ;             // AQ

    const int b  = blockIdx.z;
    const int h  = blockIdx.y;
    const int q0 = blockIdx.x * AQ;

    const int t  = threadIdx.x;
    const int tx = t & 15;
    const int ty = t >> 4;
    const int R  = ty * 4;
    const int C  = tx * 4;

    // load Q tile: thread -> (row, 16-wide d segment)
    {
        const int r  = t >> 2;
        const int c0 = (t & 3) * 16;
        const float* qp = Qb + ((size_t)b * L + q0 + r) * DMODEL + h * DK_ + c0;
        #pragma unroll
        for (int i = 0; i < 16; i += 4)
            *(float4*)&Qs[r * AST + c0 + i] = *(const float4*)(qp + i);
    }
    if (t < AQ) { mrow[t] = -1e30f; lrow[t] = 0.f; }

    float o[4][4] = {};
    const float scale_qk = 0.125f;   // 1/sqrt(64)

    for (int k0 = 0; k0 < L; k0 += AK) {
        __syncthreads();
        // load K, V tiles
        {
            const int r  = t >> 2;
            const int c0 = (t & 3) * 16;
            const float* kp = Kb + ((size_t)b * L + k0 + r) * DMODEL + h * DK_ + c0;
            const float* vp = Vb + ((size_t)b * L + k0 + r) * DMODEL + h * DK_ + c0;
            #pragma unroll
            for (int i = 0; i < 16; i += 4) {
                *(float4*)&Ks[r * AST + c0 + i] = *(const float4*)(kp + i);
                *(float4*)&Vs[r * AST + c0 + i] = *(const float4*)(vp + i);
            }
        }
        __syncthreads();

        // S = Q K^T * scale  (4x4 microtile per thread)
        {
            float s[4][4] = {};
            #pragma unroll
            for (int k = 0; k < DK_; k += 4) {
                float a4[4][4], b4[4][4];
                #pragma unroll
                for (int i = 0; i < 4; i++) {
                    float4 av = *(const float4*)&Qs[(R + i) * AST + k];
                    a4[i][0] = av.x; a4[i][1] = av.y; a4[i][2] = av.z; a4[i][3] = av.w;
                }
                #pragma unroll
                for (int j = 0; j < 4; j++) {
                    float4 bv = *(const float4*)&Ks[(C + j) * AST + k];
                    b4[j][0] = bv.x; b4[j][1] = bv.y; b4[j][2] = bv.z; b4[j][3] = bv.w;
                }
                #pragma unroll
                for (int kk = 0; kk < 4; kk++)
                    #pragma unroll
                    for (int i = 0; i < 4; i++)
                        #pragma unroll
                        for (int j = 0; j < 4; j++)
                            s[i][j] += a4[i][kk] * b4[j][kk];
            }
            #pragma unroll
            for (int j = 0; j < 4; j++) {
                const int gk = k0 + C + j;
                const bool masked = (mask[(size_t)b * L + gk] == 0);
                #pragma unroll
                for (int i = 0; i < 4; i++) {
                    float v = s[i][j] * scale_qk;
                    Ss[(R + i) * AST + C + j] = masked ? -1e9f : v;
                }
            }
        }
        __syncthreads();

        // online softmax row update (4 threads per row)
        {
            const int r   = t >> 2;
            const int seg = t & 3;
            const float mold = mrow[r];
            float rowmax = mold;
            #pragma unroll 8
            for (int c = 0; c < AK; c++)
                rowmax = fmaxf(rowmax, Ss[r * AST + c]);
            float psum = 0.f;
            #pragma unroll
            for (int c4 = 0; c4 < 4; c4++) {
                float4 e4 = *(const float4*)&Ss[r * AST + seg * 16 + c4 * 4];
                e4.x = __expf(e4.x - rowmax);
                e4.y = __expf(e4.y - rowmax);
                e4.z = __expf(e4.z - rowmax);
                e4.w = __expf(e4.w - rowmax);
                *(float4*)&Ss[r * AST + seg * 16 + c4 * 4] = e4;
                psum += e4.x + e4.y + e4.z + e4.w;
            }
            psum += __shfl_xor_sync(0xffffffffu, psum, 1);
            psum += __shfl_xor_sync(0xffffffffu, psum, 2);
            if (seg == 0) {
                const float sc = __expf(mold - rowmax);
                srow[r] = sc;
                lrow[r] = lrow[r] * sc + psum;
                mrow[r] = rowmax;
            }
        }
        __syncthreads();

        // O = O*scale + P @ V  (4x4 microtile per thread)
        {
            float sc[4];
            #pragma unroll
            for (int i = 0; i < 4; i++) sc[i] = srow[R + i];
            #pragma unroll
            for (int i = 0; i < 4; i++)
                #pragma unroll
                for (int j = 0; j < 4; j++)
                    o[i][j] *= sc[i];

            #pragma unroll
            for (int k = 0; k < AK; k += 4) {
                float pr[4][4];
                #pragma unroll
                for (int i = 0; i < 4; i++) {
                    float4 p4 = *(const float4*)&Ss[(R + i) * AST + k];
                    pr[i][0] = p4.x; pr[i][1] = p4.y; pr[i][2] = p4.z; pr[i][3] = p4.w;
                }
                #pragma unroll
                for (int kk = 0; kk < 4; kk++) {
                    float4 v4 = *(const float4*)&Vs[(k + kk) * AST + C];
                    #pragma unroll
                    for (int i = 0; i < 4; i++) {
                        o[i][0] += pr[i][kk] * v4.x;
                        o[i][1] += pr[i][kk] * v4.y;
                        o[i][2] += pr[i][kk] * v4.z;
                        o[i][3] += pr[i][kk] * v4.w;
                    }
                }
            }
        }
    }

    // epilogue: divide by l, write to (N, L, H*DK) layout
    {
        #pragma unroll
        for (int i = 0; i < 4; i++) {
            const float inv_l = 1.f / lrow[R + i];
            float4 out;
            out.x = o[i][0] * inv_l;
            out.y = o[i][1] * inv_l;
            out.z = o[i][2] * inv_l;
            out.w = o[i][3] * inv_l;
            *(float4*)&Ob[((size_t)b * L + q0 + R + i) * DMODEL + h * DK_ + C] = out;
        }
    }
}

// ---------------- launch ----------------
extern "C" void kernel_launch(void* const* d_in, const int* in_sizes, int n_in,
                              void* d_out, int out_size)
{
    const float* query = (const float*)d_in[0];
    const float* key   = (const float*)d_in[1];
    const float* value = (const float*)d_in[2];
    const int*   mask  = (const int*)d_in[3];
    const float* Wq = (const float*)d_in[4];
    const float* bq = (const float*)d_in[5];
    const float* Wk = (const float*)d_in[6];
    const float* bk = (const float*)d_in[7];
    const float* Wv = (const float*)d_in[8];
    const float* bv = (const float*)d_in[9];
    const float* Wo = (const float*)d_in[10];
    const float* bo = (const float*)d_in[11];

    const int N = NB;
    const int L = in_sizes[3] / N;    // mask is (N,1,L)
    const int M = N * L;

    float *qb, *kb, *vb, *ob;
    cudaGetSymbolAddress((void**)&qb, g_q);
    cudaGetSymbolAddress((void**)&kb, g_k);
    cudaGetSymbolAddress((void**)&vb, g_v);
    cudaGetSymbolAddress((void**)&ob, g_o);

    dim3 gblk(256);
    dim3 ggrid(DMODEL / GN, M / GM);
    gemm_nt_bias<<<ggrid, gblk>>>(query, Wq, bq, qb, M, DMODEL, DMODEL);
    gemm_nt_bias<<<ggrid, gblk>>>(key,   Wk, bk, kb, M, DMODEL, DMODEL);
    gemm_nt_bias<<<ggrid, gblk>>>(value, Wv, bv, vb, M, DMODEL, DMODEL);

    const size_t smem = (size_t)(4 * AQ * AST + 3 * AQ) * sizeof(float);
    cudaFuncSetAttribute(attn_kernel, cudaFuncAttributeMaxDynamicSharedMemorySize, (int)smem);
    attn_kernel<<<dim3(L / AQ, H_, N), 256, smem>>>(qb, kb, vb, mask, ob, L);

    gemm_nt_bias<<<ggrid, gblk>>>(ob, Wo, bo, (float*)d_out, M, DMODEL, DMODEL);
}

// round 2
// speedup vs baseline: 3.6251x; 3.6251x over previous
#include <cuda_runtime.h>
#include <math.h>

#define H_ 8
#define DMODEL 512
#define DK_ 64
#define NB 4
#define LMAX 2048

// ---------------- scratch ----------------
__device__ float g_q[NB * LMAX * DMODEL];
__device__ float g_k[NB * LMAX * DMODEL];
__device__ float g_v[NB * LMAX * DMODEL];
__device__ float g_o[NB * LMAX * DMODEL];

// ---------------- tf32 helpers ----------------
__device__ __forceinline__ unsigned f2tf32(float x) {
    unsigned r;
    asm("cvt.rna.tf32.f32 %0, %1;" : "=r"(r) : "f"(x));
    return r;
}
__device__ __forceinline__ float f2tf32f(float x) { return __uint_as_float(f2tf32(x)); }

__device__ __forceinline__ void mma_tf32(float* d, const unsigned* a, const unsigned* b) {
    asm volatile(
        "mma.sync.aligned.m16n8k8.row.col.f32.tf32.tf32.f32 "
        "{%0,%1,%2,%3},{%4,%5,%6,%7},{%8,%9},{%0,%1,%2,%3};"
        : "+f"(d[0]), "+f"(d[1]), "+f"(d[2]), "+f"(d[3])
        : "r"(a[0]), "r"(a[1]), "r"(a[2]), "r"(a[3]), "r"(b[0]), "r"(b[1]));
}
__device__ __forceinline__ float ex2(float x) {
    float y; asm("ex2.approx.ftz.f32 %0, %1;" : "=f"(y) : "f"(x)); return y;
}

// ================= tf32 NT GEMM: C[m,n] = sum_k A[m,k]*W[n,k] + bias[n] ====
// CTA 128x64, k-tile 32, 8 warps in 4(m) x 2(n), warp tile 32x32.
#define GST 36

__global__ void __launch_bounds__(256) gemm_tf32(
    const float* __restrict__ A, const float* __restrict__ W,
    const float* __restrict__ bias, float* __restrict__ C,
    int M, int N, int K)
{
    __shared__ float As[128 * GST];
    __shared__ float Bs[64 * GST];

    const int tid  = threadIdx.x;
    const int lane = tid & 31;
    const int warp = tid >> 5;
    const int g = lane >> 2;
    const int t = lane & 3;
    const int wm = warp >> 1;      // 0..3
    const int wn = warp & 1;       // 0..1
    const int m0 = blockIdx.y * 128;
    const int n0 = blockIdx.x * 64;

    // gmem load mapping (coalesced: 8 lanes cover a 32-float row chunk)
    const int lc  = (tid & 7) * 4;
    const int lar = (tid >> 3) * 4;     // A rows: 4 per thread
    const int lbr = (tid >> 3) * 2;     // B rows: 2 per thread

    const float* Ap = A + (size_t)(m0 + lar) * K + lc;
    const float* Wp = W + (size_t)(n0 + lbr) * K + lc;

    float4 pa[4], pb[2];
#pragma unroll
    for (int j = 0; j < 4; j++) pa[j] = *(const float4*)(Ap + (size_t)j * K);
#pragma unroll
    for (int j = 0; j < 2; j++) pb[j] = *(const float4*)(Wp + (size_t)j * K);

    float acc[2][4][4] = {};

    for (int k0 = 0; k0 < K; k0 += 32) {
        __syncthreads();
#pragma unroll
        for (int j = 0; j < 4; j++) {
            float4 v = pa[j];
            float4 o = make_float4(f2tf32f(v.x), f2tf32f(v.y), f2tf32f(v.z), f2tf32f(v.w));
            *(float4*)&As[(lar + j) * GST + lc] = o;
        }
#pragma unroll
        for (int j = 0; j < 2; j++) {
            float4 v = pb[j];
            float4 o = make_float4(f2tf32f(v.x), f2tf32f(v.y), f2tf32f(v.z), f2tf32f(v.w));
            *(float4*)&Bs[(lbr + j) * GST + lc] = o;
        }
        __syncthreads();

        if (k0 + 32 < K) {
#pragma unroll
            for (int j = 0; j < 4; j++) pa[j] = *(const float4*)(Ap + (size_t)j * K + k0 + 32);
#pragma unroll
            for (int j = 0; j < 2; j++) pb[j] = *(const float4*)(Wp + (size_t)j * K + k0 + 32);
        }

#pragma unroll
        for (int ks = 0; ks < 4; ks++) {
            const int kk = ks * 8;
            unsigned a[2][4], b[4][2];
#pragma unroll
            for (int mt = 0; mt < 2; mt++) {
                const int r = (wm * 32 + mt * 16 + g) * GST + kk + t;
                a[mt][0] = __float_as_uint(As[r]);
                a[mt][1] = __float_as_uint(As[r + 8 * GST]);
                a[mt][2] = __float_as_uint(As[r + 4]);
                a[mt][3] = __float_as_uint(As[r + 8 * GST + 4]);
            }
#pragma unroll
            for (int nt = 0; nt < 4; nt++) {
                const int r = (wn * 32 + nt * 8 + g) * GST + kk + t;
                b[nt][0] = __float_as_uint(Bs[r]);
                b[nt][1] = __float_as_uint(Bs[r + 4]);
            }
#pragma unroll
            for (int mt = 0; mt < 2; mt++)
#pragma unroll
                for (int nt = 0; nt < 4; nt++)
                    mma_tf32(acc[mt][nt], a[mt], b[nt]);
        }
    }

    // epilogue: bias + store (float2 per c-pair)
#pragma unroll
    for (int mt = 0; mt < 2; mt++) {
        const int row0 = m0 + wm * 32 + mt * 16 + g;
#pragma unroll
        for (int nt = 0; nt < 4; nt++) {
            const int col = n0 + wn * 32 + nt * 8 + 2 * t;
            const float b0 = bias[col], b1 = bias[col + 1];
            float2 o0 = make_float2(acc[mt][nt][0] + b0, acc[mt][nt][1] + b1);
            float2 o1 = make_float2(acc[mt][nt][2] + b0, acc[mt][nt][3] + b1);
            *(float2*)&C[(size_t)row0 * N + col]       = o0;
            *(float2*)&C[(size_t)(row0 + 8) * N + col] = o1;
        }
    }
}

// ================= flash attention, tf32 mma ==============================
// CTA: Bq=128 q-rows of one (b,h); k-tiles of 64. 8 warps, 16 q-rows each.
#define AST 72

__global__ void __launch_bounds__(256) attn_tf32(
    const float* __restrict__ Qb, const float* __restrict__ Kb,
    const float* __restrict__ Vb, const int* __restrict__ mask,
    float* __restrict__ Ob, int L)
{
    extern __shared__ float sm[];
    float* Ks   = sm;                 // 64 x 72
    float* Vs   = Ks + 64 * AST;      // 64 x 72
    float* Ss   = Vs + 64 * AST;      // 128 x 72 (P tile)
    float* madd = Ss + 128 * AST;     // 64

    const int b  = blockIdx.z;
    const int h  = blockIdx.y;
    const int q0 = blockIdx.x * 128;

    const int tid  = threadIdx.x;
    const int lane = tid & 31;
    const int warp = tid >> 5;
    const int g = lane >> 2;
    const int t = lane & 3;
    const int wr0 = warp * 16;        // warp's q-row base within tile

    // ---- load Q fragments once (direct from gmem, cvt to tf32) ----
    unsigned qa[8][4];
    {
        const float* q_r0 = Qb + ((size_t)b * L + q0 + wr0 + g) * DMODEL + h * DK_;
        const float* q_r1 = q_r0 + 8 * DMODEL;
#pragma unroll
        for (int ks = 0; ks < 8; ks++) {
            qa[ks][0] = f2tf32(q_r0[8 * ks + t]);
            qa[ks][1] = f2tf32(q_r1[8 * ks + t]);
            qa[ks][2] = f2tf32(q_r0[8 * ks + t + 4]);
            qa[ks][3] = f2tf32(q_r1[8 * ks + t + 4]);
        }
    }

    float o[8][4] = {};
    float m0r = -1e30f, m1r = -1e30f, l0 = 0.f, l1 = 0.f;
    const float SC = 0.18033688f;     // (1/sqrt(64)) * log2(e)

    // K/V gmem->smem mapping: 16 floats/thread, coalesced
    const int lc  = (tid & 15) * 4;
    const int lr0 = (tid >> 4) * 4;

    for (int k0 = 0; k0 < L; k0 += 64) {
        __syncthreads();
        {
            const float* kp = Kb + ((size_t)b * L + k0 + lr0) * DMODEL + h * DK_ + lc;
            const float* vp = Vb + ((size_t)b * L + k0 + lr0) * DMODEL + h * DK_ + lc;
#pragma unroll
            for (int j = 0; j < 4; j++) {
                float4 kv = *(const float4*)(kp + (size_t)j * DMODEL);
                float4 vv = *(const float4*)(vp + (size_t)j * DMODEL);
                *(float4*)&Ks[(lr0 + j) * AST + lc] =
                    make_float4(f2tf32f(kv.x), f2tf32f(kv.y), f2tf32f(kv.z), f2tf32f(kv.w));
                *(float4*)&Vs[(lr0 + j) * AST + lc] =
                    make_float4(f2tf32f(vv.x), f2tf32f(vv.y), f2tf32f(vv.z), f2tf32f(vv.w));
            }
            if (tid < 64)
                madd[tid] = mask[(size_t)b * L + k0 + tid] ? 0.f : -1.4427e9f;
        }
        __syncthreads();

        // ---- S = Q K^T (16 x 64 per warp), scaled+masked in exp2 domain ----
        float s[8][4];
#pragma unroll
        for (int nt = 0; nt < 8; nt++) { s[nt][0] = s[nt][1] = s[nt][2] = s[nt][3] = 0.f; }
#pragma unroll
        for (int ks = 0; ks < 8; ks++) {
            const int kk = ks * 8;
            unsigned kb[8][2];
#pragma unroll
            for (int nt = 0; nt < 8; nt++) {
                const int r = (nt * 8 + g) * AST + kk + t;
                kb[nt][0] = __float_as_uint(Ks[r]);
                kb[nt][1] = __float_as_uint(Ks[r + 4]);
            }
#pragma unroll
            for (int nt = 0; nt < 8; nt++)
                mma_tf32(s[nt], qa[ks], kb[nt]);
        }

        float rm0 = -1e30f, rm1 = -1e30f;
#pragma unroll
        for (int nt = 0; nt < 8; nt++) {
            const float ma = madd[nt * 8 + 2 * t];
            const float mb = madd[nt * 8 + 2 * t + 1];
            s[nt][0] = s[nt][0] * SC + ma;
            s[nt][1] = s[nt][1] * SC + mb;
            s[nt][2] = s[nt][2] * SC + ma;
            s[nt][3] = s[nt][3] * SC + mb;
            rm0 = fmaxf(rm0, fmaxf(s[nt][0], s[nt][1]));
            rm1 = fmaxf(rm1, fmaxf(s[nt][2], s[nt][3]));
        }
        rm0 = fmaxf(rm0, __shfl_xor_sync(0xffffffffu, rm0, 1));
        rm0 = fmaxf(rm0, __shfl_xor_sync(0xffffffffu, rm0, 2));
        rm1 = fmaxf(rm1, __shfl_xor_sync(0xffffffffu, rm1, 1));
        rm1 = fmaxf(rm1, __shfl_xor_sync(0xffffffffu, rm1, 2));
        const float mn0 = fmaxf(m0r, rm0);
        const float mn1 = fmaxf(m1r, rm1);

        float sum0 = 0.f, sum1 = 0.f;
#pragma unroll
        for (int nt = 0; nt < 8; nt++) {
            s[nt][0] = ex2(s[nt][0] - mn0);
            s[nt][1] = ex2(s[nt][1] - mn0);
            s[nt][2] = ex2(s[nt][2] - mn1);
            s[nt][3] = ex2(s[nt][3] - mn1);
            sum0 += s[nt][0] + s[nt][1];
            sum1 += s[nt][2] + s[nt][3];
        }
        sum0 += __shfl_xor_sync(0xffffffffu, sum0, 1);
        sum0 += __shfl_xor_sync(0xffffffffu, sum0, 2);
        sum1 += __shfl_xor_sync(0xffffffffu, sum1, 1);
        sum1 += __shfl_xor_sync(0xffffffffu, sum1, 2);

        const float al0 = ex2(m0r - mn0);
        const float al1 = ex2(m1r - mn1);
        l0 = l0 * al0 + sum0;
        l1 = l1 * al1 + sum1;
        m0r = mn0; m1r = mn1;

#pragma unroll
        for (int dt = 0; dt < 8; dt++) {
            o[dt][0] *= al0; o[dt][1] *= al0;
            o[dt][2] *= al1; o[dt][3] *= al1;
        }

        // store P to smem (truncated to tf32 by mma HW; values in [0,1])
#pragma unroll
        for (int nt = 0; nt < 8; nt++) {
            *(float2*)&Ss[(wr0 + g) * AST + nt * 8 + 2 * t]     = make_float2(s[nt][0], s[nt][1]);
            *(float2*)&Ss[(wr0 + g + 8) * AST + nt * 8 + 2 * t] = make_float2(s[nt][2], s[nt][3]);
        }
        __syncwarp();

        // ---- O += P @ V ----
#pragma unroll
        for (int ks = 0; ks < 8; ks++) {
            const int kk = ks * 8;
            unsigned pa[4];
            pa[0] = __float_as_uint(Ss[(wr0 + g) * AST + kk + t]);
            pa[1] = __float_as_uint(Ss[(wr0 + g + 8) * AST + kk + t]);
            pa[2] = __float_as_uint(Ss[(wr0 + g) * AST + kk + t + 4]);
            pa[3] = __float_as_uint(Ss[(wr0 + g + 8) * AST + kk + t + 4]);
            unsigned vb[8][2];
#pragma unroll
            for (int dt = 0; dt < 8; dt++) {
                vb[dt][0] = __float_as_uint(Vs[(kk + t) * AST + dt * 8 + g]);
                vb[dt][1] = __float_as_uint(Vs[(kk + t + 4) * AST + dt * 8 + g]);
            }
#pragma unroll
            for (int dt = 0; dt < 8; dt++)
                mma_tf32(o[dt], pa, vb[dt]);
        }
    }

    // ---- epilogue: O / l, write (N, L, H*DK) ----
    const float inv0 = 1.f / l0;
    const float inv1 = 1.f / l1;
    float* o_r0 = Ob + ((size_t)b * L + q0 + wr0 + g) * DMODEL + h * DK_;
    float* o_r1 = o_r0 + 8 * DMODEL;
#pragma unroll
    for (int dt = 0; dt < 8; dt++) {
        *(float2*)&o_r0[dt * 8 + 2 * t] = make_float2(o[dt][0] * inv0, o[dt][1] * inv0);
        *(float2*)&o_r1[dt * 8 + 2 * t] = make_float2(o[dt][2] * inv1, o[dt][3] * inv1);
    }
}

// ---------------- launch ----------------
extern "C" void kernel_launch(void* const* d_in, const int* in_sizes, int n_in,
                              void* d_out, int out_size)
{
    const float* query = (const float*)d_in[0];
    const float* key   = (const float*)d_in[1];
    const float* value = (const float*)d_in[2];
    const int*   mask  = (const int*)d_in[3];
    const float* Wq = (const float*)d_in[4];
    const float* bq = (const float*)d_in[5];
    const float* Wk = (const float*)d_in[6];
    const float* bk = (const float*)d_in[7];
    const float* Wv = (const float*)d_in[8];
    const float* bv = (const float*)d_in[9];
    const float* Wo = (const float*)d_in[10];
    const float* bo = (const float*)d_in[11];

    const int N = NB;
    const int L = in_sizes[3] / N;
    const int M = N * L;

    float *qb, *kb, *vb, *ob;
    cudaGetSymbolAddress((void**)&qb, g_q);
    cudaGetSymbolAddress((void**)&kb, g_k);
    cudaGetSymbolAddress((void**)&vb, g_v);
    cudaGetSymbolAddress((void**)&ob, g_o);

    dim3 ggrid(DMODEL / 64, M / 128);
    gemm_tf32<<<ggrid, 256>>>(query, Wq, bq, qb, M, DMODEL, DMODEL);
    gemm_tf32<<<ggrid, 256>>>(key,   Wk, bk, kb, M, DMODEL, DMODEL);
    gemm_tf32<<<ggrid, 256>>>(value, Wv, bv, vb, M, DMODEL, DMODEL);

    const size_t smem = (size_t)(64 * AST * 2 + 128 * AST + 64) * sizeof(float);
    cudaFuncSetAttribute(attn_tf32, cudaFuncAttributeMaxDynamicSharedMemorySize, (int)smem);
    attn_tf32<<<dim3(L / 128, H_, N), 256, smem>>>(qb, kb, vb, mask, ob, L);

    gemm_tf32<<<ggrid, 256>>>(ob, Wo, bo, (float*)d_out, M, DMODEL, DMODEL);
}

// round 3
// speedup vs baseline: 3.9435x; 1.0878x over previous
#include <cuda_runtime.h>
#include <stdint.h>

#define H_ 8
#define DMODEL 512
#define DK_ 64
#define NB 4
#define LMAX 2048

// ---------------- scratch ----------------
__device__ float g_q[NB * LMAX * DMODEL];
__device__ float g_k[NB * LMAX * DMODEL];
__device__ float g_v[NB * LMAX * DMODEL];
__device__ float g_o[NB * LMAX * DMODEL];

// ---------------- helpers ----------------
__device__ __forceinline__ unsigned f2tf32(float x) {
    unsigned r;
    asm("cvt.rna.tf32.f32 %0, %1;" : "=r"(r) : "f"(x));
    return r;
}
__device__ __forceinline__ float f2tf32f(float x) { return __uint_as_float(f2tf32(x)); }

__device__ __forceinline__ void mma_tf32(float* d, const unsigned* a, const unsigned* b) {
    asm volatile(
        "mma.sync.aligned.m16n8k8.row.col.f32.tf32.tf32.f32 "
        "{%0,%1,%2,%3},{%4,%5,%6,%7},{%8,%9},{%0,%1,%2,%3};"
        : "+f"(d[0]), "+f"(d[1]), "+f"(d[2]), "+f"(d[3])
        : "r"(a[0]), "r"(a[1]), "r"(a[2]), "r"(a[3]), "r"(b[0]), "r"(b[1]));
}
__device__ __forceinline__ float ex2(float x) {
    float y; asm("ex2.approx.ftz.f32 %0, %1;" : "=f"(y) : "f"(x)); return y;
}
__device__ __forceinline__ void cp16(uint32_t dst, const void* src) {
    asm volatile("cp.async.cg.shared.global [%0], [%1], 16;" :: "r"(dst), "l"(src));
}
#define CP_COMMIT asm volatile("cp.async.commit_group;")
#define CP_WAIT1  asm volatile("cp.async.wait_group 1;")
#define CP_WAIT0  asm volatile("cp.async.wait_group 0;")

// ================= tf32 NT GEMM (fused 3-way), cp.async 2-stage ===========
// CTA 128x64, k-tile 32, 8 warps 4(m)x2(n), warp tile 32x32.
#define GST 36
#define GSTG (192 * GST)   // floats per stage: A(128x36) + B(64x36)

__global__ void __launch_bounds__(256, 2) gemm3_tf32(
    const float* __restrict__ A0, const float* __restrict__ A1, const float* __restrict__ A2,
    const float* __restrict__ W0, const float* __restrict__ W1, const float* __restrict__ W2,
    const float* __restrict__ B0, const float* __restrict__ B1, const float* __restrict__ B2,
    float* __restrict__ C0, float* __restrict__ C1, float* __restrict__ C2,
    int M, int N, int K)
{
    extern __shared__ float sm[];
    const uint32_t smb = (uint32_t)__cvta_generic_to_shared(sm);

    const int z = blockIdx.z;
    const float* A    = (z == 0) ? A0 : (z == 1) ? A1 : A2;
    const float* W    = (z == 0) ? W0 : (z == 1) ? W1 : W2;
    const float* bias = (z == 0) ? B0 : (z == 1) ? B1 : B2;
    float*       C    = (z == 0) ? C0 : (z == 1) ? C1 : C2;

    const int tid  = threadIdx.x;
    const int lane = tid & 31;
    const int warp = tid >> 5;
    const int g = lane >> 2;
    const int t = lane & 3;
    const int wm = warp >> 1;
    const int wn = warp & 1;
    const int m0 = blockIdx.y * 128;
    const int n0 = blockIdx.x * 64;

    const int ar = tid >> 1, ac = (tid & 1) * 16;
    const int br = tid >> 2, bc = (tid & 3) * 8;
    const float* Ap = A + (size_t)(m0 + ar) * K + ac;
    const float* Wp = W + (size_t)(n0 + br) * K + bc;

    float acc[2][4][4] = {};
    const int nK = K / 32;

#define G_ISSUE(it) do {                                                   \
        const int st_ = (it) & 1;                                         \
        const int k0_ = (it) * 32;                                        \
        uint32_t ad_ = smb + (st_ * GSTG + ar * GST + ac) * 4;            \
        _Pragma("unroll")                                                  \
        for (int j = 0; j < 16; j += 4) cp16(ad_ + j * 4, Ap + k0_ + j);  \
        uint32_t bd_ = smb + (st_ * GSTG + 128 * GST + br * GST + bc) * 4;\
        _Pragma("unroll")                                                  \
        for (int j = 0; j < 8; j += 4) cp16(bd_ + j * 4, Wp + k0_ + j);   \
    } while (0)

    G_ISSUE(0); CP_COMMIT;

    for (int kt = 0; kt < nK; kt++) {
        if (kt + 1 < nK) { G_ISSUE(kt + 1); CP_COMMIT; CP_WAIT1; }
        else             { CP_WAIT0; }
        __syncthreads();

        const float* As = sm + (kt & 1) * GSTG;
        const float* Bs = As + 128 * GST;

#pragma unroll
        for (int ks = 0; ks < 4; ks++) {
            const int kk = ks * 8;
            unsigned a[2][4], bf[4][2];
#pragma unroll
            for (int mt = 0; mt < 2; mt++) {
                const int r = (wm * 32 + mt * 16 + g) * GST + kk + t;
                a[mt][0] = f2tf32(As[r]);
                a[mt][1] = f2tf32(As[r + 8 * GST]);
                a[mt][2] = f2tf32(As[r + 4]);
                a[mt][3] = f2tf32(As[r + 8 * GST + 4]);
            }
#pragma unroll
            for (int nt = 0; nt < 4; nt++) {
                const int r = (wn * 32 + nt * 8 + g) * GST + kk + t;
                bf[nt][0] = f2tf32(Bs[r]);
                bf[nt][1] = f2tf32(Bs[r + 4]);
            }
#pragma unroll
            for (int mt = 0; mt < 2; mt++)
#pragma unroll
                for (int nt = 0; nt < 4; nt++)
                    mma_tf32(acc[mt][nt], a[mt], bf[nt]);
        }
        __syncthreads();
    }

#pragma unroll
    for (int mt = 0; mt < 2; mt++) {
        const int row0 = m0 + wm * 32 + mt * 16 + g;
#pragma unroll
        for (int nt = 0; nt < 4; nt++) {
            const int col = n0 + wn * 32 + nt * 8 + 2 * t;
            const float b0 = bias[col], b1 = bias[col + 1];
            *(float2*)&C[(size_t)row0 * N + col] =
                make_float2(acc[mt][nt][0] + b0, acc[mt][nt][1] + b1);
            *(float2*)&C[(size_t)(row0 + 8) * N + col] =
                make_float2(acc[mt][nt][2] + b0, acc[mt][nt][3] + b1);
        }
    }
}

// ================= flash attention, tf32 mma, 2-stage cp.async ============
// CTA: Bq=128 q-rows of one (b,h); k-tiles of 64. 8 warps x 16 q-rows.
// K tile: 64x64 unpadded, XOR-swizzled (col ^ ((row&7)<<2)) -> conflict-free.
// V tile: 64 rows x 72 stride (natural layout is conflict-free).
#define AVST 72
#define KS_STG 4096           // floats per K stage
#define VS_STG (64 * AVST)    // 4608 floats per V stage
// smem: K[2][4096] | V[2][4608] | madd[LMAX]  = 19456 floats = 77824 B

__global__ void __launch_bounds__(256, 2) attn_tf32(
    const float* __restrict__ Qb, const float* __restrict__ Kb,
    const float* __restrict__ Vb, const int* __restrict__ mask,
    float* __restrict__ Ob, int L)
{
    extern __shared__ float sm[];
    const uint32_t smb = (uint32_t)__cvta_generic_to_shared(sm);
    float* madd = sm + 2 * KS_STG + 2 * VS_STG;

    const int b  = blockIdx.z;
    const int h  = blockIdx.y;
    const int q0 = blockIdx.x * 128;

    const int tid  = threadIdx.x;
    const int lane = tid & 31;
    const int warp = tid >> 5;
    const int g = lane >> 2;
    const int t = lane & 3;
    const int wr0 = warp * 16;

    // mask -> additive bias table for whole L (exp2 domain)
    {
        const int4* m4 = (const int4*)(mask + (size_t)b * L);
        float4* d4 = (float4*)madd;
        for (int i = tid; i < L / 4; i += 256) {
            int4 mm = m4[i];
            float4 f;
            f.x = mm.x ? 0.f : -1.4427e9f;
            f.y = mm.y ? 0.f : -1.4427e9f;
            f.z = mm.z ? 0.f : -1.4427e9f;
            f.w = mm.w ? 0.f : -1.4427e9f;
            d4[i] = f;
        }
    }

    // Q fragments, held in registers for the whole kernel
    unsigned qa[8][4];
    {
        const float* q_r0 = Qb + ((size_t)b * L + q0 + wr0 + g) * DMODEL + h * DK_;
        const float* q_r1 = q_r0 + 8 * DMODEL;
#pragma unroll
        for (int ks = 0; ks < 8; ks++) {
            qa[ks][0] = f2tf32(q_r0[8 * ks + t]);
            qa[ks][1] = f2tf32(q_r1[8 * ks + t]);
            qa[ks][2] = f2tf32(q_r0[8 * ks + t + 4]);
            qa[ks][3] = f2tf32(q_r1[8 * ks + t + 4]);
        }
    }

    float o[8][4] = {};
    float m0r = -1e30f, m1r = -1e30f, l0 = 0.f, l1 = 0.f;
    const float SC = 0.18033688f;   // (1/sqrt(64)) * log2(e)

    const int lr = tid >> 2;          // 0..63: K/V row for cp.async
    const int lcb = (tid & 3) * 16;   // col base

#define A_ISSUE(it) do {                                                       \
        const int st_ = (it) & 1;                                             \
        const int k0_ = (it) * 64;                                            \
        const float* kp_ = Kb + ((size_t)b * L + k0_ + lr) * DMODEL + h * DK_;\
        const float* vp_ = Vb + ((size_t)b * L + k0_ + lr) * DMODEL + h * DK_;\
        uint32_t kd_ = smb + (st_ * KS_STG + lr * 64) * 4;                    \
        uint32_t vd_ = smb + (2 * KS_STG + st_ * VS_STG + lr * AVST) * 4;     \
        _Pragma("unroll")                                                      \
        for (int j = 0; j < 16; j += 4) {                                     \
            const int c_ = lcb + j;                                           \
            cp16(kd_ + (c_ ^ ((lr & 7) << 2)) * 4, kp_ + c_);                 \
            cp16(vd_ + c_ * 4, vp_ + c_);                                     \
        }                                                                      \
    } while (0)

    const int nT = L / 64;
    A_ISSUE(0); CP_COMMIT;

    const int src0 = (lane & 28) | (t >> 1);
    const int src1 = src0 | 2;

    for (int it = 0; it < nT; it++) {
        if (it + 1 < nT) { A_ISSUE(it + 1); CP_COMMIT; CP_WAIT1; }
        else             { CP_WAIT0; }
        __syncthreads();

        const float* Ks = sm + (it & 1) * KS_STG;
        const float* Vs = sm + 2 * KS_STG + (it & 1) * VS_STG;
        const int k0 = it * 64;

        // ---- S = Q K^T ----
        float s[8][4];
#pragma unroll
        for (int nt = 0; nt < 8; nt++) s[nt][0] = s[nt][1] = s[nt][2] = s[nt][3] = 0.f;
#pragma unroll
        for (int ks = 0; ks < 8; ks++) {
            const int kk = ks * 8;
            unsigned kf[8][2];
#pragma unroll
            for (int nt = 0; nt < 8; nt++) {
                const int base = (nt * 8 + g) * 64;
                kf[nt][0] = f2tf32(Ks[base + ((kk + t) ^ (g << 2))]);
                kf[nt][1] = f2tf32(Ks[base + ((kk + t + 4) ^ (g << 2))]);
            }
#pragma unroll
            for (int nt = 0; nt < 8; nt++)
                mma_tf32(s[nt], qa[ks], kf[nt]);
        }

        // ---- scale + mask + online softmax (exp2 domain) ----
        float rm0 = -1e30f, rm1 = -1e30f;
#pragma unroll
        for (int nt = 0; nt < 8; nt++) {
            const float ma = madd[k0 + nt * 8 + 2 * t];
            const float mb = madd[k0 + nt * 8 + 2 * t + 1];
            s[nt][0] = s[nt][0] * SC + ma;
            s[nt][1] = s[nt][1] * SC + mb;
            s[nt][2] = s[nt][2] * SC + ma;
            s[nt][3] = s[nt][3] * SC + mb;
            rm0 = fmaxf(rm0, fmaxf(s[nt][0], s[nt][1]));
            rm1 = fmaxf(rm1, fmaxf(s[nt][2], s[nt][3]));
        }
        rm0 = fmaxf(rm0, __shfl_xor_sync(0xffffffffu, rm0, 1));
        rm0 = fmaxf(rm0, __shfl_xor_sync(0xffffffffu, rm0, 2));
        rm1 = fmaxf(rm1, __shfl_xor_sync(0xffffffffu, rm1, 1));
        rm1 = fmaxf(rm1, __shfl_xor_sync(0xffffffffu, rm1, 2));
        const float mn0 = fmaxf(m0r, rm0);
        const float mn1 = fmaxf(m1r, rm1);

        float sum0 = 0.f, sum1 = 0.f;
#pragma unroll
        for (int nt = 0; nt < 8; nt++) {
            s[nt][0] = ex2(s[nt][0] - mn0);
            s[nt][1] = ex2(s[nt][1] - mn0);
            s[nt][2] = ex2(s[nt][2] - mn1);
            s[nt][3] = ex2(s[nt][3] - mn1);
            sum0 += s[nt][0] + s[nt][1];
            sum1 += s[nt][2] + s[nt][3];
        }
        sum0 += __shfl_xor_sync(0xffffffffu, sum0, 1);
        sum0 += __shfl_xor_sync(0xffffffffu, sum0, 2);
        sum1 += __shfl_xor_sync(0xffffffffu, sum1, 1);
        sum1 += __shfl_xor_sync(0xffffffffu, sum1, 2);

        const float al0 = ex2(m0r - mn0);
        const float al1 = ex2(m1r - mn1);
        l0 = l0 * al0 + sum0;
        l1 = l1 * al1 + sum1;
        m0r = mn0; m1r = mn1;

#pragma unroll
        for (int dt = 0; dt < 8; dt++) {
            o[dt][0] *= al0; o[dt][1] *= al0;
            o[dt][2] *= al1; o[dt][3] *= al1;
        }

        // cvt P to tf32 in registers
#pragma unroll
        for (int nt = 0; nt < 8; nt++) {
            s[nt][0] = f2tf32f(s[nt][0]);
            s[nt][1] = f2tf32f(s[nt][1]);
            s[nt][2] = f2tf32f(s[nt][2]);
            s[nt][3] = f2tf32f(s[nt][3]);
        }

        // ---- O += P @ V : C-frag -> A-frag via quad shuffles ----
#pragma unroll
        for (int ks = 0; ks < 8; ks++) {
            const int kk = ks * 8;
            const float a00 = __shfl_sync(0xffffffffu, s[ks][0], src0);
            const float a01 = __shfl_sync(0xffffffffu, s[ks][1], src0);
            const float a20 = __shfl_sync(0xffffffffu, s[ks][2], src0);
            const float a21 = __shfl_sync(0xffffffffu, s[ks][3], src0);
            const float b00 = __shfl_sync(0xffffffffu, s[ks][0], src1);
            const float b01 = __shfl_sync(0xffffffffu, s[ks][1], src1);
            const float b20 = __shfl_sync(0xffffffffu, s[ks][2], src1);
            const float b21 = __shfl_sync(0xffffffffu, s[ks][3], src1);
            unsigned pa[4];
            pa[0] = __float_as_uint((t & 1) ? a01 : a00);
            pa[1] = __float_as_uint((t & 1) ? a21 : a20);
            pa[2] = __float_as_uint((t & 1) ? b01 : b00);
            pa[3] = __float_as_uint((t & 1) ? b21 : b20);

            unsigned vf[8][2];
#pragma unroll
            for (int dt = 0; dt < 8; dt++) {
                vf[dt][0] = f2tf32(Vs[(kk + t) * AVST + dt * 8 + g]);
                vf[dt][1] = f2tf32(Vs[(kk + t + 4) * AVST + dt * 8 + g]);
            }
#pragma unroll
            for (int dt = 0; dt < 8; dt++)
                mma_tf32(o[dt], pa, vf[dt]);
        }
        __syncthreads();
    }

    // ---- epilogue ----
    const float inv0 = 1.f / l0;
    const float inv1 = 1.f / l1;
    float* o_r0 = Ob + ((size_t)b * L + q0 + wr0 + g) * DMODEL + h * DK_;
    float* o_r1 = o_r0 + 8 * DMODEL;
#pragma unroll
    for (int dt = 0; dt < 8; dt++) {
        *(float2*)&o_r0[dt * 8 + 2 * t] = make_float2(o[dt][0] * inv0, o[dt][1] * inv0);
        *(float2*)&o_r1[dt * 8 + 2 * t] = make_float2(o[dt][2] * inv1, o[dt][3] * inv1);
    }
}

// ---------------- launch ----------------
extern "C" void kernel_launch(void* const* d_in, const int* in_sizes, int n_in,
                              void* d_out, int out_size)
{
    const float* query = (const float*)d_in[0];
    const float* key   = (const float*)d_in[1];
    const float* value = (const float*)d_in[2];
    const int*   mask  = (const int*)d_in[3];
    const float* Wq = (const float*)d_in[4];
    const float* bq = (const float*)d_in[5];
    const float* Wk = (const float*)d_in[6];
    const float* bk = (const float*)d_in[7];
    const float* Wv = (const float*)d_in[8];
    const float* bv = (const float*)d_in[9];
    const float* Wo = (const float*)d_in[10];
    const float* bo = (const float*)d_in[11];

    const int N = NB;
    const int L = in_sizes[3] / N;
    const int M = N * L;

    float *qb, *kb, *vb, *ob;
    cudaGetSymbolAddress((void**)&qb, g_q);
    cudaGetSymbolAddress((void**)&kb, g_k);
    cudaGetSymbolAddress((void**)&vb, g_v);
    cudaGetSymbolAddress((void**)&ob, g_o);

    const int gemm_smem = 2 * GSTG * 4;   // 55296 B
    cudaFuncSetAttribute(gemm3_tf32, cudaFuncAttributeMaxDynamicSharedMemorySize, gemm_smem);

    // fused QKV projections
    gemm3_tf32<<<dim3(DMODEL / 64, M / 128, 3), 256, gemm_smem>>>(
        query, key, value, Wq, Wk, Wv, bq, bk, bv, qb, kb, vb, M, DMODEL, DMODEL);

    const int attn_smem = (2 * KS_STG + 2 * VS_STG + LMAX) * 4;  // 77824 B
    cudaFuncSetAttribute(attn_tf32, cudaFuncAttributeMaxDynamicSharedMemorySize, attn_smem);
    attn_tf32<<<dim3(L / 128, H_, N), 256, attn_smem>>>(qb, kb, vb, mask, ob, L);

    // output projection
    gemm3_tf32<<<dim3(DMODEL / 64, M / 128, 1), 256, gemm_smem>>>(
        ob, ob, ob, Wo, Wo, Wo, bo, bo, bo, (float*)d_out, (float*)d_out, (float*)d_out,
        M, DMODEL, DMODEL);
}

// round 4
// speedup vs baseline: 4.2301x; 1.0727x over previous
#include <cuda_runtime.h>
#include <stdint.h>

#define H_ 8
#define DMODEL 512
#define DK_ 64
#define NB 4
#define LMAX 2048

// ---------------- scratch ----------------
__device__ float g_q[NB * LMAX * DMODEL];
__device__ float g_k[NB * LMAX * DMODEL];
__device__ float g_v[NB * LMAX * DMODEL];
__device__ float g_o[NB * LMAX * DMODEL];
__device__ float g_qi[NB * LMAX * DMODEL];   // tf32-rounded inputs
__device__ float g_ki[NB * LMAX * DMODEL];
__device__ float g_vi[NB * LMAX * DMODEL];
__device__ float g_w[4 * DMODEL * DMODEL];   // tf32-rounded Wq|Wk|Wv|Wo

// ---------------- helpers ----------------
__device__ __forceinline__ unsigned f2tf32(float x) {
    unsigned r;
    asm("cvt.rna.tf32.f32 %0, %1;" : "=r"(r) : "f"(x));
    return r;
}
__device__ __forceinline__ float f2tf32f(float x) { return __uint_as_float(f2tf32(x)); }

__device__ __forceinline__ void mma_tf32(float* d, const unsigned* a, const unsigned* b) {
    asm volatile(
        "mma.sync.aligned.m16n8k8.row.col.f32.tf32.tf32.f32 "
        "{%0,%1,%2,%3},{%4,%5,%6,%7},{%8,%9},{%0,%1,%2,%3};"
        : "+f"(d[0]), "+f"(d[1]), "+f"(d[2]), "+f"(d[3])
        : "r"(a[0]), "r"(a[1]), "r"(a[2]), "r"(a[3]), "r"(b[0]), "r"(b[1]));
}
__device__ __forceinline__ float ex2(float x) {
    float y; asm("ex2.approx.ftz.f32 %0, %1;" : "=f"(y) : "f"(x)); return y;
}
__device__ __forceinline__ void cp16(uint32_t dst, const void* src) {
    asm volatile("cp.async.cg.shared.global [%0], [%1], 16;" :: "r"(dst), "l"(src));
}
#define CP_COMMIT asm volatile("cp.async.commit_group;")
#define CP_WAIT1  asm volatile("cp.async.wait_group 1;")
#define CP_WAIT0  asm volatile("cp.async.wait_group 0;")

// ================= prepass: fp32 -> tf32(RNA) bulk convert ================
__global__ void __launch_bounds__(256) cvt_tf32_3(
    const float* __restrict__ s0, const float* __restrict__ s1, const float* __restrict__ s2,
    float* __restrict__ d0, float* __restrict__ d1, float* __restrict__ d2, int n4)
{
    const int z = blockIdx.z;
    const float4* s = (const float4*)((z == 0) ? s0 : (z == 1) ? s1 : s2);
    float4*       d = (float4*)((z == 0) ? d0 : (z == 1) ? d1 : d2);
    for (int i = blockIdx.x * 256 + threadIdx.x; i < n4; i += gridDim.x * 256) {
        float4 v = s[i];
        d[i] = make_float4(f2tf32f(v.x), f2tf32f(v.y), f2tf32f(v.z), f2tf32f(v.w));
    }
}
__global__ void __launch_bounds__(256) cvt_tf32_w(
    const float* __restrict__ w0, const float* __restrict__ w1,
    const float* __restrict__ w2, const float* __restrict__ w3,
    float* __restrict__ dst, int n4)
{
    const int z = blockIdx.z;
    const float4* s = (const float4*)((z == 0) ? w0 : (z == 1) ? w1 : (z == 2) ? w2 : w3);
    float4*       d = (float4*)(dst + (size_t)z * DMODEL * DMODEL);
    for (int i = blockIdx.x * 256 + threadIdx.x; i < n4; i += gridDim.x * 256) {
        float4 v = s[i];
        d[i] = make_float4(f2tf32f(v.x), f2tf32f(v.y), f2tf32f(v.z), f2tf32f(v.w));
    }
}

// ================= tf32 NT GEMM (fused 3-way), cp.async 2-stage ===========
// CTA 128x128, k-tile 32, 8 warps 4(m)x2(n), warp tile 32x64.
// Inputs are pre-rounded tf32; no cvt in the hot loop.
#define GST 36
#define GSTG (256 * GST)   // floats/stage: A(128x36) + B(128x36)

__global__ void __launch_bounds__(256, 2) gemm3_tf32(
    const float* __restrict__ A0, const float* __restrict__ A1, const float* __restrict__ A2,
    const float* __restrict__ Wt, int w_off,
    const float* __restrict__ B0, const float* __restrict__ B1, const float* __restrict__ B2,
    float* __restrict__ C0, float* __restrict__ C1, float* __restrict__ C2,
    int M, int N, int K, int round_out)
{
    extern __shared__ float sm[];
    const uint32_t smb = (uint32_t)__cvta_generic_to_shared(sm);

    const int z = blockIdx.z;
    const float* A    = (z == 0) ? A0 : (z == 1) ? A1 : A2;
    const float* W    = Wt + (size_t)(w_off + z) * DMODEL * DMODEL;
    const float* bias = (z == 0) ? B0 : (z == 1) ? B1 : B2;
    float*       C    = (z == 0) ? C0 : (z == 1) ? C1 : C2;

    const int tid  = threadIdx.x;
    const int lane = tid & 31;
    const int warp = tid >> 5;
    const int g = lane >> 2;
    const int t = lane & 3;
    const int wm = warp >> 1;
    const int wn = warp & 1;
    const int m0 = blockIdx.y * 128;
    const int n0 = blockIdx.x * 128;

    const int lr = tid >> 1, lc = (tid & 1) * 16;
    const float* Ap = A + (size_t)(m0 + lr) * K + lc;
    const float* Wp = W + (size_t)(n0 + lr) * K + lc;

    float acc[2][8][4] = {};
    const int nK = K / 32;

#define G_ISSUE(it) do {                                                   \
        const int st_ = (it) & 1;                                         \
        const int k0_ = (it) * 32;                                        \
        uint32_t ad_ = smb + (st_ * GSTG + lr * GST + lc) * 4;            \
        uint32_t bd_ = smb + (st_ * GSTG + 128 * GST + lr * GST + lc) * 4;\
        _Pragma("unroll")                                                  \
        for (int j = 0; j < 16; j += 4) {                                 \
            cp16(ad_ + j * 4, Ap + k0_ + j);                              \
            cp16(bd_ + j * 4, Wp + k0_ + j);                              \
        }                                                                  \
    } while (0)

    G_ISSUE(0); CP_COMMIT;

    for (int kt = 0; kt < nK; kt++) {
        if (kt + 1 < nK) { G_ISSUE(kt + 1); CP_COMMIT; CP_WAIT1; }
        else             { CP_WAIT0; }
        __syncthreads();

        const unsigned* As = (const unsigned*)(sm + (kt & 1) * GSTG);
        const unsigned* Bs = As + 128 * GST;

#pragma unroll
        for (int ks = 0; ks < 4; ks++) {
            const int kk = ks * 8;
            unsigned a[2][4], bf[8][2];
#pragma unroll
            for (int mt = 0; mt < 2; mt++) {
                const int r = (wm * 32 + mt * 16 + g) * GST + kk + t;
                a[mt][0] = As[r];
                a[mt][1] = As[r + 8 * GST];
                a[mt][2] = As[r + 4];
                a[mt][3] = As[r + 8 * GST + 4];
            }
#pragma unroll
            for (int nt = 0; nt < 8; nt++) {
                const int r = (wn * 64 + nt * 8 + g) * GST + kk + t;
                bf[nt][0] = Bs[r];
                bf[nt][1] = Bs[r + 4];
            }
#pragma unroll
            for (int mt = 0; mt < 2; mt++)
#pragma unroll
                for (int nt = 0; nt < 8; nt++)
                    mma_tf32(acc[mt][nt], a[mt], bf[nt]);
        }
        __syncthreads();
    }

#pragma unroll
    for (int mt = 0; mt < 2; mt++) {
        const int row0 = m0 + wm * 32 + mt * 16 + g;
#pragma unroll
        for (int nt = 0; nt < 8; nt++) {
            const int col = n0 + wn * 64 + nt * 8 + 2 * t;
            const float b0 = bias[col], b1 = bias[col + 1];
            float v00 = acc[mt][nt][0] + b0, v01 = acc[mt][nt][1] + b1;
            float v10 = acc[mt][nt][2] + b0, v11 = acc[mt][nt][3] + b1;
            if (round_out) {
                v00 = f2tf32f(v00); v01 = f2tf32f(v01);
                v10 = f2tf32f(v10); v11 = f2tf32f(v11);
            }
            *(float2*)&C[(size_t)row0 * N + col]       = make_float2(v00, v01);
            *(float2*)&C[(size_t)(row0 + 8) * N + col] = make_float2(v10, v11);
        }
    }
}

// ================= flash attention, tf32 mma, 2-stage cp.async ============
// All operands pre-rounded tf32; only P gets a cvt.
#define AVST 72
#define KS_STG 4096
#define VS_STG (64 * AVST)

__global__ void __launch_bounds__(256, 2) attn_tf32(
    const float* __restrict__ Qb, const float* __restrict__ Kb,
    const float* __restrict__ Vb, const int* __restrict__ mask,
    float* __restrict__ Ob, int L)
{
    extern __shared__ float sm[];
    const uint32_t smb = (uint32_t)__cvta_generic_to_shared(sm);
    float* madd = sm + 2 * KS_STG + 2 * VS_STG;

    const int b  = blockIdx.z;
    const int h  = blockIdx.y;
    const int q0 = blockIdx.x * 128;

    const int tid  = threadIdx.x;
    const int lane = tid & 31;
    const int warp = tid >> 5;
    const int g = lane >> 2;
    const int t = lane & 3;
    const int wr0 = warp * 16;

    {
        const int4* m4 = (const int4*)(mask + (size_t)b * L);
        float4* d4 = (float4*)madd;
        for (int i = tid; i < L / 4; i += 256) {
            int4 mm = m4[i];
            float4 f;
            f.x = mm.x ? 0.f : -1.4427e9f;
            f.y = mm.y ? 0.f : -1.4427e9f;
            f.z = mm.z ? 0.f : -1.4427e9f;
            f.w = mm.w ? 0.f : -1.4427e9f;
            d4[i] = f;
        }
    }

    // Q fragments (already tf32 in gmem)
    unsigned qa[8][4];
    {
        const float* q_r0 = Qb + ((size_t)b * L + q0 + wr0 + g) * DMODEL + h * DK_;
        const float* q_r1 = q_r0 + 8 * DMODEL;
#pragma unroll
        for (int ks = 0; ks < 8; ks++) {
            qa[ks][0] = __float_as_uint(q_r0[8 * ks + t]);
            qa[ks][1] = __float_as_uint(q_r1[8 * ks + t]);
            qa[ks][2] = __float_as_uint(q_r0[8 * ks + t + 4]);
            qa[ks][3] = __float_as_uint(q_r1[8 * ks + t + 4]);
        }
    }

    float o[8][4] = {};
    float m0r = -1e30f, m1r = -1e30f, l0 = 0.f, l1 = 0.f;
    const float SC = 0.18033688f;   // (1/sqrt(64)) * log2(e)

    const int lr = tid >> 2;
    const int lcb = (tid & 3) * 16;

#define A_ISSUE(it) do {                                                       \
        const int st_ = (it) & 1;                                             \
        const int k0_ = (it) * 64;                                            \
        const float* kp_ = Kb + ((size_t)b * L + k0_ + lr) * DMODEL + h * DK_;\
        const float* vp_ = Vb + ((size_t)b * L + k0_ + lr) * DMODEL + h * DK_;\
        uint32_t kd_ = smb + (st_ * KS_STG + lr * 64) * 4;                    \
        uint32_t vd_ = smb + (2 * KS_STG + st_ * VS_STG + lr * AVST) * 4;     \
        _Pragma("unroll")                                                      \
        for (int j = 0; j < 16; j += 4) {                                     \
            const int c_ = lcb + j;                                           \
            cp16(kd_ + (c_ ^ ((lr & 7) << 2)) * 4, kp_ + c_);                 \
            cp16(vd_ + c_ * 4, vp_ + c_);                                     \
        }                                                                      \
    } while (0)

    const int nT = L / 64;
    A_ISSUE(0); CP_COMMIT;

    const int src0 = (lane & 28) | (t >> 1);
    const int src1 = src0 | 2;

    for (int it = 0; it < nT; it++) {
        if (it + 1 < nT) { A_ISSUE(it + 1); CP_COMMIT; CP_WAIT1; }
        else             { CP_WAIT0; }
        __syncthreads();

        const unsigned* Ks = (const unsigned*)(sm + (it & 1) * KS_STG);
        const unsigned* Vs = (const unsigned*)(sm + 2 * KS_STG + (it & 1) * VS_STG);
        const int k0 = it * 64;

        // ---- S = Q K^T ----
        float s[8][4];
#pragma unroll
        for (int nt = 0; nt < 8; nt++) s[nt][0] = s[nt][1] = s[nt][2] = s[nt][3] = 0.f;
#pragma unroll
        for (int ks = 0; ks < 8; ks++) {
            const int kk = ks * 8;
            unsigned kf[8][2];
#pragma unroll
            for (int nt = 0; nt < 8; nt++) {
                const int base = (nt * 8 + g) * 64;
                kf[nt][0] = Ks[base + ((kk + t) ^ (g << 2))];
                kf[nt][1] = Ks[base + ((kk + t + 4) ^ (g << 2))];
            }
#pragma unroll
            for (int nt = 0; nt < 8; nt++)
                mma_tf32(s[nt], qa[ks], kf[nt]);
        }

        // ---- scale + mask + online softmax (exp2 domain) ----
        float rm0 = -1e30f, rm1 = -1e30f;
#pragma unroll
        for (int nt = 0; nt < 8; nt++) {
            const float ma = madd[k0 + nt * 8 + 2 * t];
            const float mb = madd[k0 + nt * 8 + 2 * t + 1];
            s[nt][0] = s[nt][0] * SC + ma;
            s[nt][1] = s[nt][1] * SC + mb;
            s[nt][2] = s[nt][2] * SC + ma;
            s[nt][3] = s[nt][3] * SC + mb;
            rm0 = fmaxf(rm0, fmaxf(s[nt][0], s[nt][1]));
            rm1 = fmaxf(rm1, fmaxf(s[nt][2], s[nt][3]));
        }
        rm0 = fmaxf(rm0, __shfl_xor_sync(0xffffffffu, rm0, 1));
        rm0 = fmaxf(rm0, __shfl_xor_sync(0xffffffffu, rm0, 2));
        rm1 = fmaxf(rm1, __shfl_xor_sync(0xffffffffu, rm1, 1));
        rm1 = fmaxf(rm1, __shfl_xor_sync(0xffffffffu, rm1, 2));
        const float mn0 = fmaxf(m0r, rm0);
        const float mn1 = fmaxf(m1r, rm1);

        float sum0 = 0.f, sum1 = 0.f;
#pragma unroll
        for (int nt = 0; nt < 8; nt++) {
            s[nt][0] = ex2(s[nt][0] - mn0);
            s[nt][1] = ex2(s[nt][1] - mn0);
            s[nt][2] = ex2(s[nt][2] - mn1);
            s[nt][3] = ex2(s[nt][3] - mn1);
            sum0 += s[nt][0] + s[nt][1];
            sum1 += s[nt][2] + s[nt][3];
        }
        sum0 += __shfl_xor_sync(0xffffffffu, sum0, 1);
        sum0 += __shfl_xor_sync(0xffffffffu, sum0, 2);
        sum1 += __shfl_xor_sync(0xffffffffu, sum1, 1);
        sum1 += __shfl_xor_sync(0xffffffffu, sum1, 2);

        const float al0 = ex2(m0r - mn0);
        const float al1 = ex2(m1r - mn1);
        l0 = l0 * al0 + sum0;
        l1 = l1 * al1 + sum1;
        m0r = mn0; m1r = mn1;

#pragma unroll
        for (int dt = 0; dt < 8; dt++) {
            o[dt][0] *= al0; o[dt][1] *= al0;
            o[dt][2] *= al1; o[dt][3] *= al1;
        }

        // P -> tf32 (RNA)
#pragma unroll
        for (int nt = 0; nt < 8; nt++) {
            s[nt][0] = f2tf32f(s[nt][0]);
            s[nt][1] = f2tf32f(s[nt][1]);
            s[nt][2] = f2tf32f(s[nt][2]);
            s[nt][3] = f2tf32f(s[nt][3]);
        }

        // ---- O += P @ V : C-frag -> A-frag via quad shuffles ----
#pragma unroll
        for (int ks = 0; ks < 8; ks++) {
            const int kk = ks * 8;
            const float a00 = __shfl_sync(0xffffffffu, s[ks][0], src0);
            const float a01 = __shfl_sync(0xffffffffu, s[ks][1], src0);
            const float a20 = __shfl_sync(0xffffffffu, s[ks][2], src0);
            const float a21 = __shfl_sync(0xffffffffu, s[ks][3], src0);
            const float b00 = __shfl_sync(0xffffffffu, s[ks][0], src1);
            const float b01 = __shfl_sync(0xffffffffu, s[ks][1], src1);
            const float b20 = __shfl_sync(0xffffffffu, s[ks][2], src1);
            const float b21 = __shfl_sync(0xffffffffu, s[ks][3], src1);
            unsigned pa[4];
            pa[0] = __float_as_uint((t & 1) ? a01 : a00);
            pa[1] = __float_as_uint((t & 1) ? a21 : a20);
            pa[2] = __float_as_uint((t & 1) ? b01 : b00);
            pa[3] = __float_as_uint((t & 1) ? b21 : b20);

            unsigned vf[8][2];
#pragma unroll
            for (int dt = 0; dt < 8; dt++) {
                vf[dt][0] = Vs[(kk + t) * AVST + dt * 8 + g];
                vf[dt][1] = Vs[(kk + t + 4) * AVST + dt * 8 + g];
            }
#pragma unroll
            for (int dt = 0; dt < 8; dt++)
                mma_tf32(o[dt], pa, vf[dt]);
        }
        __syncthreads();
    }

    // ---- epilogue: write tf32-rounded O (consumed by tf32 out-proj) ----
    const float inv0 = 1.f / l0;
    const float inv1 = 1.f / l1;
    float* o_r0 = Ob + ((size_t)b * L + q0 + wr0 + g) * DMODEL + h * DK_;
    float* o_r1 = o_r0 + 8 * DMODEL;
#pragma unroll
    for (int dt = 0; dt < 8; dt++) {
        *(float2*)&o_r0[dt * 8 + 2 * t] =
            make_float2(f2tf32f(o[dt][0] * inv0), f2tf32f(o[dt][1] * inv0));
        *(float2*)&o_r1[dt * 8 + 2 * t] =
            make_float2(f2tf32f(o[dt][2] * inv1), f2tf32f(o[dt][3] * inv1));
    }
}

// ---------------- launch ----------------
extern "C" void kernel_launch(void* const* d_in, const int* in_sizes, int n_in,
                              void* d_out, int out_size)
{
    const float* query = (const float*)d_in[0];
    const float* key   = (const float*)d_in[1];
    const float* value = (const float*)d_in[2];
    const int*   mask  = (const int*)d_in[3];
    const float* Wq = (const float*)d_in[4];
    const float* bq = (const float*)d_in[5];
    const float* Wk = (const float*)d_in[6];
    const float* bk = (const float*)d_in[7];
    const float* Wv = (const float*)d_in[8];
    const float* bv = (const float*)d_in[9];
    const float* Wo = (const float*)d_in[10];
    const float* bo = (const float*)d_in[11];

    const int N = NB;
    const int L = in_sizes[3] / N;
    const int M = N * L;

    float *qb, *kb, *vb, *ob, *qi, *ki, *vi, *wb;
    cudaGetSymbolAddress((void**)&qb, g_q);
    cudaGetSymbolAddress((void**)&kb, g_k);
    cudaGetSymbolAddress((void**)&vb, g_v);
    cudaGetSymbolAddress((void**)&ob, g_o);
    cudaGetSymbolAddress((void**)&qi, g_qi);
    cudaGetSymbolAddress((void**)&ki, g_ki);
    cudaGetSymbolAddress((void**)&vi, g_vi);
    cudaGetSymbolAddress((void**)&wb, g_w);

    // prepass: tf32-round inputs + weights
    const int n4_in = M * DMODEL / 4;
    cvt_tf32_3<<<dim3(512, 1, 3), 256>>>(query, key, value, qi, ki, vi, n4_in);
    const int n4_w = DMODEL * DMODEL / 4;
    cvt_tf32_w<<<dim3(128, 1, 4), 256>>>(Wq, Wk, Wv, Wo, wb, n4_w);

    const int gemm_smem = 2 * GSTG * 4;   // 73728 B
    cudaFuncSetAttribute(gemm3_tf32, cudaFuncAttributeMaxDynamicSharedMemorySize, gemm_smem);

    // fused QKV projections (round outputs to tf32)
    gemm3_tf32<<<dim3(DMODEL / 128, M / 128, 3), 256, gemm_smem>>>(
        qi, ki, vi, wb, 0, bq, bk, bv, qb, kb, vb, M, DMODEL, DMODEL, 1);

    const int attn_smem = (2 * KS_STG + 2 * VS_STG + LMAX) * 4;  // 77824 B
    cudaFuncSetAttribute(attn_tf32, cudaFuncAttributeMaxDynamicSharedMemorySize, attn_smem);
    attn_tf32<<<dim3(L / 128, H_, N), 256, attn_smem>>>(qb, kb, vb, mask, ob, L);

    // output projection (fp32 output, no rounding)
    gemm3_tf32<<<dim3(DMODEL / 128, M / 128, 1), 256, gemm_smem>>>(
        ob, ob, ob, wb, 3, bo, bo, bo, (float*)d_out, (float*)d_out, (float*)d_out,
        M, DMODEL, DMODEL, 0);
}

// round 5
// speedup vs baseline: 4.3708x; 1.0333x over previous
#include <cuda_runtime.h>
#include <stdint.h>

#define H_ 8
#define DMODEL 512
#define DK_ 64
#define NB 4
#define LMAX 2048

// ---------------- scratch ----------------
__device__ float g_q[NB * LMAX * DMODEL];
__device__ float g_k[NB * LMAX * DMODEL];
__device__ float g_v[NB * LMAX * DMODEL];   // holds V TRANSPOSED: [(b*512+dcol)][token]
__device__ float g_o[NB * LMAX * DMODEL];
__device__ float g_qi[NB * LMAX * DMODEL];  // tf32-rounded inputs
__device__ float g_ki[NB * LMAX * DMODEL];
__device__ float g_vi[NB * LMAX * DMODEL];
__device__ float g_w[4 * DMODEL * DMODEL];  // tf32-rounded Wq|Wk|Wv|Wo

// ---------------- helpers ----------------
__device__ __forceinline__ unsigned f2tf32(float x) {
    unsigned r;
    asm("cvt.rna.tf32.f32 %0, %1;" : "=r"(r) : "f"(x));
    return r;
}
__device__ __forceinline__ float f2tf32f(float x) { return __uint_as_float(f2tf32(x)); }

__device__ __forceinline__ void mma_tf32(float* d, const unsigned* a, unsigned b0, unsigned b1) {
    asm volatile(
        "mma.sync.aligned.m16n8k8.row.col.f32.tf32.tf32.f32 "
        "{%0,%1,%2,%3},{%4,%5,%6,%7},{%8,%9},{%0,%1,%2,%3};"
        : "+f"(d[0]), "+f"(d[1]), "+f"(d[2]), "+f"(d[3])
        : "r"(a[0]), "r"(a[1]), "r"(a[2]), "r"(a[3]), "r"(b0), "r"(b1));
}
__device__ __forceinline__ void ldsm4(unsigned& r0, unsigned& r1, unsigned& r2, unsigned& r3,
                                      uint32_t addr) {
    asm volatile("ldmatrix.sync.aligned.m8n8.x4.shared.b16 {%0,%1,%2,%3}, [%4];"
                 : "=r"(r0), "=r"(r1), "=r"(r2), "=r"(r3) : "r"(addr));
}
__device__ __forceinline__ float ex2(float x) {
    float y; asm("ex2.approx.ftz.f32 %0, %1;" : "=f"(y) : "f"(x)); return y;
}
__device__ __forceinline__ void cp16(uint32_t dst, const void* src) {
    asm volatile("cp.async.cg.shared.global [%0], [%1], 16;" :: "r"(dst), "l"(src));
}
#define CP_COMMIT asm volatile("cp.async.commit_group;")
#define CP_WAIT1  asm volatile("cp.async.wait_group 1;")
#define CP_WAIT0  asm volatile("cp.async.wait_group 0;")

// ================= prepass: fp32 -> tf32(RNA) bulk convert ================
__global__ void __launch_bounds__(256) cvt_tf32_3(
    const float* __restrict__ s0, const float* __restrict__ s1, const float* __restrict__ s2,
    float* __restrict__ d0, float* __restrict__ d1, float* __restrict__ d2, int n4)
{
    const int z = blockIdx.z;
    const float4* s = (const float4*)((z == 0) ? s0 : (z == 1) ? s1 : s2);
    float4*       d = (float4*)((z == 0) ? d0 : (z == 1) ? d1 : d2);
    for (int i = blockIdx.x * 256 + threadIdx.x; i < n4; i += gridDim.x * 256) {
        float4 v = s[i];
        d[i] = make_float4(f2tf32f(v.x), f2tf32f(v.y), f2tf32f(v.z), f2tf32f(v.w));
    }
}
__global__ void __launch_bounds__(256) cvt_tf32_w(
    const float* __restrict__ w0, const float* __restrict__ w1,
    const float* __restrict__ w2, const float* __restrict__ w3,
    float* __restrict__ dst, int n4)
{
    const int z = blockIdx.z;
    const float4* s = (const float4*)((z == 0) ? w0 : (z == 1) ? w1 : (z == 2) ? w2 : w3);
    float4*       d = (float4*)(dst + (size_t)z * DMODEL * DMODEL);
    for (int i = blockIdx.x * 256 + threadIdx.x; i < n4; i += gridDim.x * 256) {
        float4 v = s[i];
        d[i] = make_float4(f2tf32f(v.x), f2tf32f(v.y), f2tf32f(v.z), f2tf32f(v.w));
    }
}

// ================= tf32 NT GEMM (fused 3-way), ldmatrix + cp.async ========
// CTA 128x128, k-tile 32, 8 warps 4(m)x2(n), warp tile 32x64.
#define GST 36
#define GSTG (256 * GST)

__global__ void __launch_bounds__(256, 2) gemm3_tf32(
    const float* __restrict__ A0, const float* __restrict__ A1, const float* __restrict__ A2,
    const float* __restrict__ Wt, int w_off,
    const float* __restrict__ B0, const float* __restrict__ B1, const float* __restrict__ B2,
    float* __restrict__ C0, float* __restrict__ C1, float* __restrict__ C2,
    int M, int N, int K, int round_out, int Lpar, int vt_mode)
{
    extern __shared__ float sm[];
    const uint32_t smb = (uint32_t)__cvta_generic_to_shared(sm);

    const int z = blockIdx.z;
    const float* A    = (z == 0) ? A0 : (z == 1) ? A1 : A2;
    const float* W    = Wt + (size_t)(w_off + z) * DMODEL * DMODEL;
    const float* bias = (z == 0) ? B0 : (z == 1) ? B1 : B2;
    float*       C    = (z == 0) ? C0 : (z == 1) ? C1 : C2;
    const bool   vt   = (z == 2) && vt_mode;

    const int tid  = threadIdx.x;
    const int lane = tid & 31;
    const int warp = tid >> 5;
    const int g = lane >> 2;
    const int t = lane & 3;
    const int wm = warp >> 1;
    const int wn = warp & 1;
    const int m0 = blockIdx.y * 128;
    const int n0 = blockIdx.x * 128;

    const int lr = tid >> 1, lc = (tid & 1) * 16;
    const float* Ap = A + (size_t)(m0 + lr) * K + lc;
    const float* Wp = W + (size_t)(n0 + lr) * K + lc;

    // ldmatrix per-lane row terms
    const int afr   = (lane & 8) + (lane & 7);   // 0..15
    const int acoff = (lane & 16) >> 2;          // 0 or 4
    int rta[2], rtb[4];
#pragma unroll
    for (int mt = 0; mt < 2; mt++) rta[mt] = (wm * 32 + mt * 16 + afr) * GST + acoff;
#pragma unroll
    for (int p = 0; p < 4; p++) rtb[p] = (wn * 64 + p * 16 + (lane & 15)) * GST + acoff;

    float acc[2][8][4] = {};
    const int nK = K / 32;

#define G_ISSUE(it) do {                                                   \
        const int st_ = (it) & 1;                                         \
        const int k0_ = (it) * 32;                                        \
        uint32_t ad_ = smb + (st_ * GSTG + lr * GST + lc) * 4;            \
        uint32_t bd_ = smb + (st_ * GSTG + 128 * GST + lr * GST + lc) * 4;\
        _Pragma("unroll")                                                  \
        for (int j = 0; j < 16; j += 4) {                                 \
            cp16(ad_ + j * 4, Ap + k0_ + j);                              \
            cp16(bd_ + j * 4, Wp + k0_ + j);                              \
        }                                                                  \
    } while (0)

    G_ISSUE(0); CP_COMMIT;

    for (int kt = 0; kt < nK; kt++) {
        if (kt + 1 < nK) { G_ISSUE(kt + 1); CP_COMMIT; CP_WAIT1; }
        else             { CP_WAIT0; }
        __syncthreads();

        const uint32_t smA = smb + ((kt & 1) * GSTG) * 4;
        const uint32_t smB = smA + 128 * GST * 4;

#pragma unroll
        for (int ks = 0; ks < 4; ks++) {
            const int kk = ks * 8;
            unsigned a[2][4], bf[4][4];
#pragma unroll
            for (int mt = 0; mt < 2; mt++)
                ldsm4(a[mt][0], a[mt][1], a[mt][2], a[mt][3], smA + (rta[mt] + kk) * 4);
#pragma unroll
            for (int p = 0; p < 4; p++)
                ldsm4(bf[p][0], bf[p][1], bf[p][2], bf[p][3], smB + (rtb[p] + kk) * 4);
#pragma unroll
            for (int mt = 0; mt < 2; mt++)
#pragma unroll
                for (int p = 0; p < 4; p++) {
                    mma_tf32(acc[mt][2 * p],     a[mt], bf[p][0], bf[p][2]);
                    mma_tf32(acc[mt][2 * p + 1], a[mt], bf[p][1], bf[p][3]);
                }
        }
        __syncthreads();
    }

#pragma unroll
    for (int mt = 0; mt < 2; mt++) {
        const int row0 = m0 + wm * 32 + mt * 16 + g;
#pragma unroll
        for (int nt = 0; nt < 8; nt++) {
            const int col = n0 + wn * 64 + nt * 8 + 2 * t;
            const float b0 = bias[col], b1 = bias[col + 1];
            float v00 = acc[mt][nt][0] + b0, v01 = acc[mt][nt][1] + b1;
            float v10 = acc[mt][nt][2] + b0, v11 = acc[mt][nt][3] + b1;
            if (round_out) {
                v00 = f2tf32f(v00); v01 = f2tf32f(v01);
                v10 = f2tf32f(v10); v11 = f2tf32f(v11);
            }
            if (vt) {
                // transposed store: addr = (b*DMODEL + col)*L + token
                const int bI  = row0 / Lpar;
                const int tok = row0 - bI * Lpar;
                float* base0 = C + (size_t)(bI * DMODEL + col) * Lpar;
                float* base1 = base0 + Lpar;
                base0[tok]     = v00;  base1[tok]     = v01;
                base0[tok + 8] = v10;  base1[tok + 8] = v11;
            } else {
                *(float2*)&C[(size_t)row0 * N + col]       = make_float2(v00, v01);
                *(float2*)&C[(size_t)(row0 + 8) * N + col] = make_float2(v10, v11);
            }
        }
    }
}

// ================= flash attention: ldmatrix fragments ====================
// K tile: 64x64 (token-major), V tile: 64x64 (d-major, from transposed gmem),
// both XOR-swizzled (col ^ ((row&7)<<2)); 2-stage cp.async.
#define TS_STG 4096
// smem: K[2][4096] | V[2][4096] | madd[LMAX] = 18432 floats = 73728 B

__global__ void __launch_bounds__(256, 2) attn_tf32(
    const float* __restrict__ Qb, const float* __restrict__ Kb,
    const float* __restrict__ Vt, const int* __restrict__ mask,
    float* __restrict__ Ob, int L)
{
    extern __shared__ float sm[];
    const uint32_t smb = (uint32_t)__cvta_generic_to_shared(sm);
    float* madd = sm + 4 * TS_STG;

    const int b  = blockIdx.z;
    const int h  = blockIdx.y;
    const int q0 = blockIdx.x * 128;

    const int tid  = threadIdx.x;
    const int lane = tid & 31;
    const int warp = tid >> 5;
    const int g = lane >> 2;
    const int t = lane & 3;
    const int wr0 = warp * 16;

    {
        const int4* m4 = (const int4*)(mask + (size_t)b * L);
        float4* d4 = (float4*)madd;
        for (int i = tid; i < L / 4; i += 256) {
            int4 mm = m4[i];
            float4 f;
            f.x = mm.x ? 0.f : -1.4427e9f;
            f.y = mm.y ? 0.f : -1.4427e9f;
            f.z = mm.z ? 0.f : -1.4427e9f;
            f.w = mm.w ? 0.f : -1.4427e9f;
            d4[i] = f;
        }
    }

    // Q fragments (already tf32 in gmem)
    unsigned qa[8][4];
    {
        const float* q_r0 = Qb + ((size_t)b * L + q0 + wr0 + g) * DMODEL + h * DK_;
        const float* q_r1 = q_r0 + 8 * DMODEL;
#pragma unroll
        for (int ks = 0; ks < 8; ks++) {
            qa[ks][0] = __float_as_uint(q_r0[8 * ks + t]);
            qa[ks][1] = __float_as_uint(q_r1[8 * ks + t]);
            qa[ks][2] = __float_as_uint(q_r0[8 * ks + t + 4]);
            qa[ks][3] = __float_as_uint(q_r1[8 * ks + t + 4]);
        }
    }

    float o[8][4] = {};
    float m0r = -1e30f, m1r = -1e30f, l0 = 0.f, l1 = 0.f;
    const float SC = 0.18033688f;   // (1/sqrt(64)) * log2(e)

    // ldmatrix per-lane row terms (same for K and V tiles)
    const int frow  = lane & 15;            // row within 16-row block
    const int fcoff = (lane & 16) >> 2;     // 0 or 4
    const int fxr   = (lane & 7) << 2;      // xor term for that row
    int rt[4];
#pragma unroll
    for (int p = 0; p < 4; p++) rt[p] = (p * 16 + frow) * 64;

    const int lr  = tid >> 2;         // row for cp.async
    const int lcb = (tid & 3) * 16;

#define A_ISSUE(it) do {                                                        \
        const int st_ = (it) & 1;                                              \
        const int k0_ = (it) * 64;                                             \
        const float* kp_ = Kb + ((size_t)b * L + k0_ + lr) * DMODEL + h * DK_; \
        const float* vp_ = Vt + ((size_t)(b * DMODEL + h * DK_ + lr)) * L + k0_;\
        uint32_t kd_ = smb + (st_ * TS_STG + lr * 64) * 4;                     \
        uint32_t vd_ = smb + ((2 + st_) * TS_STG + lr * 64) * 4;               \
        const int xw_ = (lr & 7) << 2;                                         \
        _Pragma("unroll")                                                       \
        for (int j = 0; j < 16; j += 4) {                                      \
            const int c_ = lcb + j;                                            \
            cp16(kd_ + (c_ ^ xw_) * 4, kp_ + c_);                              \
            cp16(vd_ + (c_ ^ xw_) * 4, vp_ + c_);                              \
        }                                                                       \
    } while (0)

    const int nT = L / 64;
    A_ISSUE(0); CP_COMMIT;

    const int src0 = (lane & 28) | (t >> 1);
    const int src1 = src0 | 2;

    for (int it = 0; it < nT; it++) {
        if (it + 1 < nT) { A_ISSUE(it + 1); CP_COMMIT; CP_WAIT1; }
        else             { CP_WAIT0; }
        __syncthreads();

        const uint32_t smK = smb + ((it & 1) * TS_STG) * 4;
        const uint32_t smV = smb + ((2 + (it & 1)) * TS_STG) * 4;
        const int k0 = it * 64;

        // ---- S = Q K^T ----
        float s[8][4];
#pragma unroll
        for (int nt = 0; nt < 8; nt++) s[nt][0] = s[nt][1] = s[nt][2] = s[nt][3] = 0.f;
#pragma unroll
        for (int ks = 0; ks < 8; ks++) {
            const int csw = ((ks * 8 + fcoff) ^ fxr) * 4;
            unsigned kf[4][4];
#pragma unroll
            for (int p = 0; p < 4; p++)
                ldsm4(kf[p][0], kf[p][1], kf[p][2], kf[p][3], smK + rt[p] * 4 + csw);
#pragma unroll
            for (int p = 0; p < 4; p++) {
                mma_tf32(s[2 * p],     qa[ks], kf[p][0], kf[p][2]);
                mma_tf32(s[2 * p + 1], qa[ks], kf[p][1], kf[p][3]);
            }
        }

        // ---- scale + mask + online softmax (exp2 domain) ----
        float rm0 = -1e30f, rm1 = -1e30f;
#pragma unroll
        for (int nt = 0; nt < 8; nt++) {
            const float ma = madd[k0 + nt * 8 + 2 * t];
            const float mb = madd[k0 + nt * 8 + 2 * t + 1];
            s[nt][0] = s[nt][0] * SC + ma;
            s[nt][1] = s[nt][1] * SC + mb;
            s[nt][2] = s[nt][2] * SC + ma;
            s[nt][3] = s[nt][3] * SC + mb;
            rm0 = fmaxf(rm0, fmaxf(s[nt][0], s[nt][1]));
            rm1 = fmaxf(rm1, fmaxf(s[nt][2], s[nt][3]));
        }
        rm0 = fmaxf(rm0, __shfl_xor_sync(0xffffffffu, rm0, 1));
        rm0 = fmaxf(rm0, __shfl_xor_sync(0xffffffffu, rm0, 2));
        rm1 = fmaxf(rm1, __shfl_xor_sync(0xffffffffu, rm1, 1));
        rm1 = fmaxf(rm1, __shfl_xor_sync(0xffffffffu, rm1, 2));
        const float mn0 = fmaxf(m0r, rm0);
        const float mn1 = fmaxf(m1r, rm1);

        float sum0 = 0.f, sum1 = 0.f;
#pragma unroll
        for (int nt = 0; nt < 8; nt++) {
            s[nt][0] = ex2(s[nt][0] - mn0);
            s[nt][1] = ex2(s[nt][1] - mn0);
            s[nt][2] = ex2(s[nt][2] - mn1);
            s[nt][3] = ex2(s[nt][3] - mn1);
            sum0 += s[nt][0] + s[nt][1];
            sum1 += s[nt][2] + s[nt][3];
        }
        sum0 += __shfl_xor_sync(0xffffffffu, sum0, 1);
        sum0 += __shfl_xor_sync(0xffffffffu, sum0, 2);
        sum1 += __shfl_xor_sync(0xffffffffu, sum1, 1);
        sum1 += __shfl_xor_sync(0xffffffffu, sum1, 2);

        const float al0 = ex2(m0r - mn0);
        const float al1 = ex2(m1r - mn1);
        l0 = l0 * al0 + sum0;
        l1 = l1 * al1 + sum1;
        m0r = mn0; m1r = mn1;

#pragma unroll
        for (int dt = 0; dt < 8; dt++) {
            o[dt][0] *= al0; o[dt][1] *= al0;
            o[dt][2] *= al1; o[dt][3] *= al1;
        }

        // P -> tf32 (RNA)
#pragma unroll
        for (int nt = 0; nt < 8; nt++) {
            s[nt][0] = f2tf32f(s[nt][0]);
            s[nt][1] = f2tf32f(s[nt][1]);
            s[nt][2] = f2tf32f(s[nt][2]);
            s[nt][3] = f2tf32f(s[nt][3]);
        }

        // ---- O += P @ V : C-frag -> A-frag via quad shuffles; V via ldmatrix ----
#pragma unroll
        for (int ks = 0; ks < 8; ks++) {
            const float a00 = __shfl_sync(0xffffffffu, s[ks][0], src0);
            const float a01 = __shfl_sync(0xffffffffu, s[ks][1], src0);
            const float a20 = __shfl_sync(0xffffffffu, s[ks][2], src0);
            const float a21 = __shfl_sync(0xffffffffu, s[ks][3], src0);
            const float b00 = __shfl_sync(0xffffffffu, s[ks][0], src1);
            const float b01 = __shfl_sync(0xffffffffu, s[ks][1], src1);
            const float b20 = __shfl_sync(0xffffffffu, s[ks][2], src1);
            const float b21 = __shfl_sync(0xffffffffu, s[ks][3], src1);
            unsigned pa[4];
            pa[0] = __float_as_uint((t & 1) ? a01 : a00);
            pa[1] = __float_as_uint((t & 1) ? a21 : a20);
            pa[2] = __float_as_uint((t & 1) ? b01 : b00);
            pa[3] = __float_as_uint((t & 1) ? b21 : b20);

            const int csw = ((ks * 8 + fcoff) ^ fxr) * 4;
            unsigned vf[4][4];
#pragma unroll
            for (int p = 0; p < 4; p++)
                ldsm4(vf[p][0], vf[p][1], vf[p][2], vf[p][3], smV + rt[p] * 4 + csw);
#pragma unroll
            for (int p = 0; p < 4; p++) {
                mma_tf32(o[2 * p],     pa, vf[p][0], vf[p][2]);
                mma_tf32(o[2 * p + 1], pa, vf[p][1], vf[p][3]);
            }
        }
        __syncthreads();
    }

    // ---- epilogue: write tf32-rounded O ----
    const float inv0 = 1.f / l0;
    const float inv1 = 1.f / l1;
    float* o_r0 = Ob + ((size_t)b * L + q0 + wr0 + g) * DMODEL + h * DK_;
    float* o_r1 = o_r0 + 8 * DMODEL;
#pragma unroll
    for (int dt = 0; dt < 8; dt++) {
        *(float2*)&o_r0[dt * 8 + 2 * t] =
            make_float2(f2tf32f(o[dt][0] * inv0), f2tf32f(o[dt][1] * inv0));
        *(float2*)&o_r1[dt * 8 + 2 * t] =
            make_float2(f2tf32f(o[dt][2] * inv1), f2tf32f(o[dt][3] * inv1));
    }
}

// ---------------- launch ----------------
extern "C" void kernel_launch(void* const* d_in, const int* in_sizes, int n_in,
                              void* d_out, int out_size)
{
    const float* query = (const float*)d_in[0];
    const float* key   = (const float*)d_in[1];
    const float* value = (const float*)d_in[2];
    const int*   mask  = (const int*)d_in[3];
    const float* Wq = (const float*)d_in[4];
    const float* bq = (const float*)d_in[5];
    const float* Wk = (const float*)d_in[6];
    const float* bk = (const float*)d_in[7];
    const float* Wv = (const float*)d_in[8];
    const float* bv = (const float*)d_in[9];
    const float* Wo = (const float*)d_in[10];
    const float* bo = (const float*)d_in[11];

    const int N = NB;
    const int L = in_sizes[3] / N;
    const int M = N * L;

    float *qb, *kb, *vb, *ob, *qi, *ki, *vi, *wb;
    cudaGetSymbolAddress((void**)&qb, g_q);
    cudaGetSymbolAddress((void**)&kb, g_k);
    cudaGetSymbolAddress((void**)&vb, g_v);
    cudaGetSymbolAddress((void**)&ob, g_o);
    cudaGetSymbolAddress((void**)&qi, g_qi);
    cudaGetSymbolAddress((void**)&ki, g_ki);
    cudaGetSymbolAddress((void**)&vi, g_vi);
    cudaGetSymbolAddress((void**)&wb, g_w);

    // prepass: tf32-round inputs + weights
    const int n4_in = M * DMODEL / 4;
    cvt_tf32_3<<<dim3(512, 1, 3), 256>>>(query, key, value, qi, ki, vi, n4_in);
    const int n4_w = DMODEL * DMODEL / 4;
    cvt_tf32_w<<<dim3(128, 1, 4), 256>>>(Wq, Wk, Wv, Wo, wb, n4_w);

    const int gemm_smem = 2 * GSTG * 4;   // 73728 B
    cudaFuncSetAttribute(gemm3_tf32, cudaFuncAttributeMaxDynamicSharedMemorySize, gemm_smem);

    // fused QKV projections (tf32-rounded outputs; V stored transposed)
    gemm3_tf32<<<dim3(DMODEL / 128, M / 128, 3), 256, gemm_smem>>>(
        qi, ki, vi, wb, 0, bq, bk, bv, qb, kb, vb, M, DMODEL, DMODEL, 1, L, 1);

    const int attn_smem = (4 * TS_STG + LMAX) * 4;  // 73728 B
    cudaFuncSetAttribute(attn_tf32, cudaFuncAttributeMaxDynamicSharedMemorySize, attn_smem);
    attn_tf32<<<dim3(L / 128, H_, N), 256, attn_smem>>>(qb, kb, vb, mask, ob, L);

    // output projection (fp32 output)
    gemm3_tf32<<<dim3(DMODEL / 128, M / 128, 1), 256, gemm_smem>>>(
        ob, ob, ob, wb, 3, bo, bo, bo, (float*)d_out, (float*)d_out, (float*)d_out,
        M, DMODEL, DMODEL, 0, L, 0);
}